// round 9
// baseline (speedup 1.0000x reference)
#include <cuda_runtime.h>
#include <cuda_bf16.h>
#include <cstdint>

#define MAXN 2048
#define MARGIN 0.2f

__device__ double   g_acc[4];   // [0]=sabs, [1]=prec_count, [2]=possum, [3]=dn
__device__ unsigned g_count;    // last-block-finalize counter (reset each run)

// ---------------------------------------------------------------------------
__device__ __forceinline__ void mma_tf32(float* c, const uint32_t* a, const uint32_t* b) {
    asm volatile(
        "mma.sync.aligned.m16n8k8.row.col.f32.tf32.tf32.f32 "
        "{%0,%1,%2,%3}, {%4,%5,%6,%7}, {%8,%9}, {%0,%1,%2,%3};\n"
        : "+f"(c[0]), "+f"(c[1]), "+f"(c[2]), "+f"(c[3])
        : "r"(a[0]), "r"(a[1]), "r"(a[2]), "r"(a[3]), "r"(b[0]), "r"(b[1]));
}

__device__ __forceinline__ float fast_sqrt(float v) {
    float r;
    asm("rsqrt.approx.f32 %0, %1;" : "=f"(r) : "f"(v));
    return v * r;   // v clamped >= 1e-12 upstream
}

// ---------------------------------------------------------------------------
// Single-launch fused kernel: symmetric 64x64 tiles (upper triangle), 256 thr,
// 8 warps, warp tile 16x32 -> 16 acc regs/thread, target 4 blocks/SM.
// Positive distances computed in-block (labels grouped in aligned 8-blocks).
// Epilogue: two passes; pass A stores d into the dead acc regs, pass B reuses.
__global__ __launch_bounds__(256, 4)
void fused_kernel(const float* __restrict__ x, const int* __restrict__ tg,
                  const int* __restrict__ ni, int N, int D, int nBlocks,
                  float* __restrict__ out) {
    __shared__ float As[64][36];
    __shared__ float Bs[64][36];
    __shared__ float s_tA[64][8], s_tB[64][8];
    __shared__ float s_sqA[64], s_sqB[64];
    __shared__ int   s_lA[64], s_lB[64];
    __shared__ float s_red[4][8];

    // post-GEMM scratch aliased onto the (dead) A/B tiles
    float (*s_dotA)[8][8] = (float (*)[8][8])&As[0][0];   // [8][8][8]
    float (*s_dotB)[8][8] = (float (*)[8][8])&Bs[0][0];

    const int tid  = threadIdx.x;
    const int lane = tid & 31;
    const int warp = tid >> 5;
    const int wm   = warp >> 1;   // 0..3 (16-row slices)
    const int wn   = warp & 1;    // 0..1 (32-col slices)
    const int g    = lane >> 2;   // 0..7
    const int q    = lane & 3;    // 0..3

    // decode triangular tile index (bx >= by)
    const int T = N >> 6;
    int by = 0, rem = blockIdx.x, rowlen = T;
    while (rem >= rowlen) { rem -= rowlen; by++; rowlen--; }
    const int bx = by + rem;
    const int rowBase = by * 64;
    const int colBase = bx * 64;
    const bool diag = (bx == by);

    if (tid < 64) {
        s_lA[tid] = tg[rowBase + tid];
        s_lB[tid] = tg[colBase + tid];
    }

    // pos-pair assignment: 512 ordered pairs per side, 2 consecutive per thread
    const int p0  = tid * 2;
    const int pgp = p0 >> 6;          // group 0..7
    const int pa  = (p0 >> 3) & 7;    // row-in-group
    const int pb0 = p0 & 7;           // col base (even)
    const int iA  = pgp * 8 + pa;

    float acc[4][4];                  // [nt][frag]: m16n8 frags over 32 cols
    #pragma unroll
    for (int nt = 0; nt < 4; nt++)
        #pragma unroll
        for (int r = 0; r < 4; r++) acc[nt][r] = 0.f;

    float dotA[2] = {0.f, 0.f};
    float dotB[2] = {0.f, 0.f};

    for (int kc = 0; kc < D; kc += 32) {
        __syncthreads();
        for (int t = tid; t < 64 * 8; t += 256) {
            int r  = t >> 3;
            int c4 = (t & 7) << 2;
            *(float4*)&As[r][c4] = *(const float4*)&x[(size_t)(rowBase + r) * D + kc + c4];
            *(float4*)&Bs[r][c4] = *(const float4*)&x[(size_t)(colBase + r) * D + kc + c4];
        }
        __syncthreads();

        // ---- tensor-core GEMM on the chunk ----
        #pragma unroll
        for (int kk = 0; kk < 32; kk += 8) {
            uint32_t a[4];
            {
                int r0 = wm * 16 + g;
                a[0] = __float_as_uint(As[r0][kk + q]);
                a[1] = __float_as_uint(As[r0 + 8][kk + q]);
                a[2] = __float_as_uint(As[r0][kk + q + 4]);
                a[3] = __float_as_uint(As[r0 + 8][kk + q + 4]);
            }
            uint32_t b[4][2];
            #pragma unroll
            for (int nt = 0; nt < 4; nt++) {
                int c0 = wn * 32 + nt * 8 + g;
                b[nt][0] = __float_as_uint(Bs[c0][kk + q]);
                b[nt][1] = __float_as_uint(Bs[c0][kk + q + 4]);
            }
            #pragma unroll
            for (int nt = 0; nt < 4; nt++)
                mma_tf32(acc[nt], a, b[nt]);
        }

        // ---- intra-group positive dot partials (fp32 scalar) ----
        #pragma unroll
        for (int k4 = 0; k4 < 8; k4++) {
            float4 av = *(const float4*)&As[iA][k4 * 4];
            float4 bv = *(const float4*)&Bs[iA][k4 * 4];
            #pragma unroll
            for (int jj = 0; jj < 2; jj++) {
                float4 aj = *(const float4*)&As[pgp * 8 + pb0 + jj][k4 * 4];
                dotA[jj] = fmaf(av.x, aj.x, fmaf(av.y, aj.y, fmaf(av.z, aj.z, fmaf(av.w, aj.w, dotA[jj]))));
                float4 bj = *(const float4*)&Bs[pgp * 8 + pb0 + jj][k4 * 4];
                dotB[jj] = fmaf(bv.x, bj.x, fmaf(bv.y, bj.y, fmaf(bv.z, bj.z, fmaf(bv.w, bj.w, dotB[jj]))));
            }
        }
    }
    __syncthreads();

    // publish pos dots into aliased scratch (tiles now dead)
    #pragma unroll
    for (int jj = 0; jj < 2; jj++) {
        s_dotA[pgp][pa][pb0 + jj] = dotA[jj];
        s_dotB[pgp][pa][pb0 + jj] = dotB[jj];
    }
    __syncthreads();

    // fill t-tables + norms: tid<64 -> rows, 64<=tid<128 -> cols
    float psum = 0.f;
    if (tid < 128) {
        const int r   = tid & 63;
        const int gp2 = r >> 3;
        const int a2  = r & 7;
        float (*dot)[8][8] = (tid < 64) ? s_dotA : s_dotB;
        float (*tarr)[8]   = (tid < 64) ? s_tA   : s_tB;
        float sqa = dot[gp2][a2][a2];
        if (tid < 64) s_sqA[r] = sqa; else s_sqB[r] = sqa;
        int idx = 0;
        #pragma unroll
        for (int j = 0; j < 8; j++) {
            if (j != a2) {
                float d2 = fmaxf(sqa + dot[gp2][j][j] - 2.f * dot[gp2][a2][j], 1e-12f);
                float d  = fast_sqrt(d2);
                tarr[r][idx++] = d + MARGIN;
                if (diag && tid < 64) psum += d;   // possum once per anchor (diag tiles)
            }
        }
        tarr[r][7] = 0.f;
    }
    __syncthreads();

    // -------------------- epilogue pass A: rows outer --------------------
    float sabsA0 = 0.f, sabsA1 = 0.f, sabsB0 = 0.f, sabsB1 = 0.f;
    float pcA = 0.f, pcB = 0.f;
    float dnacc = 0.f;

    #pragma unroll
    for (int h = 0; h < 2; h++) {
        const int r = wm * 16 + h * 8 + g;
        const int i = rowBase + r;
        const float sqa = s_sqA[r];
        const int   la  = s_lA[r];
        float ta0 = s_tA[r][0], ta1 = s_tA[r][1], ta2 = s_tA[r][2];
        float ta3 = s_tA[r][3], ta4 = s_tA[r][4], ta5 = s_tA[r][5];
        float ta6 = s_tA[r][6];
        #pragma unroll
        for (int nt = 0; nt < 4; nt++) {
            #pragma unroll
            for (int v = 0; v < 2; v++) {
                const int c = wn * 32 + nt * 8 + 2 * q + v;
                const int j = colBase + c;
                float m = ((diag && j <= i) || (la == s_lB[c])) ? 0.f : 1.f;
                float d2 = fmaxf(sqa + s_sqB[c] - 2.f * acc[nt][h * 2 + v], 1e-12f);
                float d  = fast_sqrt(d2);
                acc[nt][h * 2 + v] = d;        // cache d for pass B
                dnacc = fmaf(m, d, dnacc);
                float dl;
                dl = ta0 - d; sabsA0 = fmaf(m, fabsf(dl), sabsA0); if (dl < MARGIN) pcA += m;
                dl = ta1 - d; sabsA1 = fmaf(m, fabsf(dl), sabsA1); if (dl < MARGIN) pcA += m;
                dl = ta2 - d; sabsA0 = fmaf(m, fabsf(dl), sabsA0); if (dl < MARGIN) pcA += m;
                dl = ta3 - d; sabsA1 = fmaf(m, fabsf(dl), sabsA1); if (dl < MARGIN) pcA += m;
                dl = ta4 - d; sabsA0 = fmaf(m, fabsf(dl), sabsA0); if (dl < MARGIN) pcA += m;
                dl = ta5 - d; sabsA1 = fmaf(m, fabsf(dl), sabsA1); if (dl < MARGIN) pcA += m;
                dl = ta6 - d; sabsA0 = fmaf(m, fabsf(dl), sabsA0); if (dl < MARGIN) pcA += m;
            }
        }
    }

    // -------------------- epilogue pass B: cols outer --------------------
    #pragma unroll
    for (int nt = 0; nt < 4; nt++) {
        #pragma unroll
        for (int v = 0; v < 2; v++) {
            const int c = wn * 32 + nt * 8 + 2 * q + v;
            const int j = colBase + c;
            const int lb = s_lB[c];
            float tb0 = s_tB[c][0], tb1 = s_tB[c][1], tb2 = s_tB[c][2];
            float tb3 = s_tB[c][3], tb4 = s_tB[c][4], tb5 = s_tB[c][5];
            float tb6 = s_tB[c][6];
            #pragma unroll
            for (int h = 0; h < 2; h++) {
                const int r = wm * 16 + h * 8 + g;
                const int i = rowBase + r;
                float m = ((diag && j <= i) || (s_lA[r] == lb)) ? 0.f : 1.f;
                float d = acc[nt][h * 2 + v];
                float dl;
                dl = tb0 - d; sabsB0 = fmaf(m, fabsf(dl), sabsB0); if (dl < MARGIN) pcB += m;
                dl = tb1 - d; sabsB1 = fmaf(m, fabsf(dl), sabsB1); if (dl < MARGIN) pcB += m;
                dl = tb2 - d; sabsB0 = fmaf(m, fabsf(dl), sabsB0); if (dl < MARGIN) pcB += m;
                dl = tb3 - d; sabsB1 = fmaf(m, fabsf(dl), sabsB1); if (dl < MARGIN) pcB += m;
                dl = tb4 - d; sabsB0 = fmaf(m, fabsf(dl), sabsB0); if (dl < MARGIN) pcB += m;
                dl = tb5 - d; sabsB1 = fmaf(m, fabsf(dl), sabsB1); if (dl < MARGIN) pcB += m;
                dl = tb6 - d; sabsB0 = fmaf(m, fabsf(dl), sabsB0); if (dl < MARGIN) pcB += m;
            }
        }
    }

    // block reduction of (sabs, dn*2, pc, psum)
    float v4[4] = { (sabsA0 + sabsA1) + (sabsB0 + sabsB1),
                    2.f * dnacc,
                    pcA + pcB,
                    psum };
    #pragma unroll
    for (int r = 0; r < 4; r++) {
        float s = v4[r];
        #pragma unroll
        for (int o = 16; o > 0; o >>= 1) s += __shfl_xor_sync(0xffffffffu, s, o);
        if (lane == 0) s_red[r][warp] = s;
    }
    __syncthreads();

    if (warp == 0) {
        if (lane < 4) {
            float s = 0.f;
            #pragma unroll
            for (int w = 0; w < 8; w++) s += s_red[lane][w];
            // lane0->sabs(0), lane1->dn(3), lane2->pc(1), lane3->possum(2)
            const int dst[4] = {0, 3, 1, 2};
            atomicAdd(&g_acc[dst[lane]], (double)s);
        }
        __syncwarp();
        if (lane == 0) {
            __threadfence();
            unsigned old = atomicAdd(&g_count, 1u);
            if (old == (unsigned)(nBlocks - 1)) {
                double sabs   = atomicAdd(&g_acc[0], 0.0);
                double pc     = atomicAdd(&g_acc[1], 0.0);
                double possum = atomicAdd(&g_acc[2], 0.0);
                double dn     = atomicAdd(&g_acc[3], 0.0);
                int K = ni[0];
                double npos = (double)(K - 1);
                double nneg = (double)(N - K);
                double T_total = possum + (double)N * npos * (double)MARGIN;
                double hinge   = 0.5 * (nneg * T_total - npos * dn + sabs);
                double cnt     = (double)N * npos * nneg;
                out[0] = (float)(hinge / cnt);
                out[1] = (float)(pc / cnt);
                out[2] = (float)(possum / ((double)N * npos));
                out[3] = (float)(dn / ((double)N * nneg));
                g_acc[0] = 0.0; g_acc[1] = 0.0; g_acc[2] = 0.0; g_acc[3] = 0.0;
                __threadfence();
                g_count = 0u;
            }
        }
    }
}

// ---------------------------------------------------------------------------
extern "C" void kernel_launch(void* const* d_in, const int* in_sizes, int n_in,
                              void* d_out, int out_size) {
    const float* x  = (const float*)d_in[0];
    const int*   tg = (const int*)d_in[1];
    const int*   ni = (const int*)d_in[2];
    float*       out = (float*)d_out;

    const int N = in_sizes[1];
    const int D = in_sizes[0] / N;
    const int T = N / 64;
    const int nTiles = T * (T + 1) / 2;

    fused_kernel<<<nTiles, 256>>>(x, tg, ni, N, D, nTiles, out);
}

// round 10
// speedup vs baseline: 1.3168x; 1.3168x over previous
#include <cuda_runtime.h>
#include <cuda_bf16.h>
#include <cstdint>

#define MAXN 2048
#define MARGIN 0.2f

__device__ double   g_acc[4];   // [0]=sabs, [1]=prec_count, [2]=possum, [3]=dn
__device__ unsigned g_count;    // last-block-finalize counter (reset each run)

// ---------------------------------------------------------------------------
__device__ __forceinline__ void mma_tf32(float* c, const uint32_t* a, const uint32_t* b) {
    asm volatile(
        "mma.sync.aligned.m16n8k8.row.col.f32.tf32.tf32.f32 "
        "{%0,%1,%2,%3}, {%4,%5,%6,%7}, {%8,%9}, {%0,%1,%2,%3};\n"
        : "+f"(c[0]), "+f"(c[1]), "+f"(c[2]), "+f"(c[3])
        : "r"(a[0]), "r"(a[1]), "r"(a[2]), "r"(a[3]), "r"(b[0]), "r"(b[1]));
}

__device__ __forceinline__ float fast_sqrt(float v) {
    float r;
    asm("rsqrt.approx.f32 %0, %1;" : "=f"(r) : "f"(v));
    return v * r;   // v clamped >= 1e-12 upstream
}

// ---------------------------------------------------------------------------
// Single-launch fused kernel, 512 threads, 128x128 triangular tiles.
// Labels are grouped in aligned 8-blocks => off-diag tiles have NO same-label
// pairs (mask-free fast path); diag tiles use m = (c>>3) > (r>>3).
// Epilogue: two passes; pass A caches d in the dead acc regs, pass B reuses.
__global__ __launch_bounds__(512)
void fused_kernel(const float* __restrict__ x, const int* __restrict__ tg,
                  const int* __restrict__ ni, int N, int D, int nBlocks,
                  float* __restrict__ out) {
    __shared__ float As[128][36];
    __shared__ float Bs[128][36];
    __shared__ float s_tA[128][8], s_tB[128][8];
    __shared__ float s_sqA[128], s_sqB[128];
    __shared__ float s_red[4][16];

    // post-GEMM scratch aliased onto the (dead) A/B tiles
    float (*s_dotA)[8][8] = (float (*)[8][8])&As[0][0];   // [16][8][8]
    float (*s_dotB)[8][8] = (float (*)[8][8])&Bs[0][0];

    const int tid  = threadIdx.x;
    const int lane = tid & 31;
    const int warp = tid >> 5;
    const int wm   = warp >> 2;   // 0..3
    const int wn   = warp & 3;    // 0..3
    const int g    = lane >> 2;   // 0..7
    const int q    = lane & 3;    // 0..3

    // decode triangular tile index (bx >= by)
    const int T = N >> 7;
    int by = 0, rem = blockIdx.x, rowlen = T;
    while (rem >= rowlen) { rem -= rowlen; by++; rowlen--; }
    const int bx = by + rem;
    const int rowBase = by * 128;
    const int colBase = bx * 128;
    const bool diag = (bx == by);

    // pos-pair assignment: 1024 ordered pairs per side, 2 consecutive per thread
    const int p0  = tid * 2;
    const int pgp = p0 >> 6;          // group 0..15
    const int pa  = (p0 >> 3) & 7;    // row-in-group
    const int pb0 = p0 & 7;           // col base (even)
    const int iA  = pgp * 8 + pa;

    float acc[2][4][4];
    #pragma unroll
    for (int mt = 0; mt < 2; mt++)
        #pragma unroll
        for (int nt = 0; nt < 4; nt++)
            #pragma unroll
            for (int r = 0; r < 4; r++) acc[mt][nt][r] = 0.f;

    float dotA[2] = {0.f, 0.f};
    float dotB[2] = {0.f, 0.f};

    for (int kc = 0; kc < D; kc += 32) {
        __syncthreads();
        for (int t = tid; t < 128 * 8; t += 512) {
            int r  = t >> 3;
            int c4 = (t & 7) << 2;
            *(float4*)&As[r][c4] = *(const float4*)&x[(size_t)(rowBase + r) * D + kc + c4];
            *(float4*)&Bs[r][c4] = *(const float4*)&x[(size_t)(colBase + r) * D + kc + c4];
        }
        __syncthreads();

        // ---- tensor-core GEMM on the chunk ----
        #pragma unroll
        for (int kk = 0; kk < 32; kk += 8) {
            uint32_t a[2][4];
            #pragma unroll
            for (int mt = 0; mt < 2; mt++) {
                int r0 = wm * 32 + mt * 16 + g;
                a[mt][0] = __float_as_uint(As[r0][kk + q]);
                a[mt][1] = __float_as_uint(As[r0 + 8][kk + q]);
                a[mt][2] = __float_as_uint(As[r0][kk + q + 4]);
                a[mt][3] = __float_as_uint(As[r0 + 8][kk + q + 4]);
            }
            uint32_t b[4][2];
            #pragma unroll
            for (int nt = 0; nt < 4; nt++) {
                int c0 = wn * 32 + nt * 8 + g;
                b[nt][0] = __float_as_uint(Bs[c0][kk + q]);
                b[nt][1] = __float_as_uint(Bs[c0][kk + q + 4]);
            }
            #pragma unroll
            for (int mt = 0; mt < 2; mt++)
                #pragma unroll
                for (int nt = 0; nt < 4; nt++)
                    mma_tf32(acc[mt][nt], a[mt], b[nt]);
        }

        // ---- intra-group positive dot partials (fp32 scalar) ----
        #pragma unroll
        for (int k4 = 0; k4 < 8; k4++) {
            float4 av = *(const float4*)&As[iA][k4 * 4];
            float4 bv = *(const float4*)&Bs[iA][k4 * 4];
            #pragma unroll
            for (int jj = 0; jj < 2; jj++) {
                float4 aj = *(const float4*)&As[pgp * 8 + pb0 + jj][k4 * 4];
                dotA[jj] = fmaf(av.x, aj.x, fmaf(av.y, aj.y, fmaf(av.z, aj.z, fmaf(av.w, aj.w, dotA[jj]))));
                float4 bj = *(const float4*)&Bs[pgp * 8 + pb0 + jj][k4 * 4];
                dotB[jj] = fmaf(bv.x, bj.x, fmaf(bv.y, bj.y, fmaf(bv.z, bj.z, fmaf(bv.w, bj.w, dotB[jj]))));
            }
        }
    }
    __syncthreads();

    // publish pos dots into aliased scratch (tiles now dead)
    #pragma unroll
    for (int jj = 0; jj < 2; jj++) {
        s_dotA[pgp][pa][pb0 + jj] = dotA[jj];
        s_dotB[pgp][pa][pb0 + jj] = dotB[jj];
    }
    __syncthreads();

    // fill t-tables + norms: tid<128 -> rows, 128<=tid<256 -> cols
    float psum = 0.f;
    if (tid < 256) {
        const int r   = tid & 127;
        const int gp2 = r >> 3;
        const int a2  = r & 7;
        float (*dot)[8][8] = (tid < 128) ? s_dotA : s_dotB;
        float (*tarr)[8]   = (tid < 128) ? s_tA   : s_tB;
        float sqa = dot[gp2][a2][a2];
        if (tid < 128) s_sqA[r] = sqa; else s_sqB[r] = sqa;
        int idx = 0;
        #pragma unroll
        for (int j = 0; j < 8; j++) {
            if (j != a2) {
                float d2 = fmaxf(sqa + dot[gp2][j][j] - 2.f * dot[gp2][a2][j], 1e-12f);
                float d  = fast_sqrt(d2);
                tarr[r][idx++] = d + MARGIN;
                if (diag && tid < 128) psum += d;   // possum once per anchor (diag tiles)
            }
        }
        tarr[r][7] = 0.f;
    }
    __syncthreads();

    // -------------------- epilogue --------------------
    float sabsA0 = 0.f, sabsA1 = 0.f, sabsB0 = 0.f, sabsB1 = 0.f;
    float pcA = 0.f, pcB = 0.f;
    float dnacc = 0.f;

    // preload this thread's 8 column norms (fixed columns)
    float sqb_r[8];
    #pragma unroll
    for (int nt = 0; nt < 4; nt++)
        #pragma unroll
        for (int v = 0; v < 2; v++)
            sqb_r[nt * 2 + v] = s_sqB[wn * 32 + nt * 8 + 2 * q + v];

    if (!diag) {
        // ======== fast path: every pair is cross-label, no masks ========
        // pass A: rows outer
        #pragma unroll
        for (int mt = 0; mt < 2; mt++) {
            #pragma unroll
            for (int h = 0; h < 2; h++) {
                const int r = wm * 32 + mt * 16 + h * 8 + g;
                const float sqa = s_sqA[r];
                float ta0 = s_tA[r][0], ta1 = s_tA[r][1], ta2 = s_tA[r][2];
                float ta3 = s_tA[r][3], ta4 = s_tA[r][4], ta5 = s_tA[r][5];
                float ta6 = s_tA[r][6];
                #pragma unroll
                for (int nt = 0; nt < 4; nt++) {
                    #pragma unroll
                    for (int v = 0; v < 2; v++) {
                        float d2 = fmaxf(sqa + sqb_r[nt * 2 + v] - 2.f * acc[mt][nt][h * 2 + v], 1e-12f);
                        float d  = fast_sqrt(d2);
                        acc[mt][nt][h * 2 + v] = d;        // cache for pass B
                        dnacc += d;
                        float dl;
                        dl = ta0 - d; sabsA0 += fabsf(dl); if (dl < MARGIN) pcA += 1.f;
                        dl = ta1 - d; sabsA1 += fabsf(dl); if (dl < MARGIN) pcA += 1.f;
                        dl = ta2 - d; sabsA0 += fabsf(dl); if (dl < MARGIN) pcA += 1.f;
                        dl = ta3 - d; sabsA1 += fabsf(dl); if (dl < MARGIN) pcA += 1.f;
                        dl = ta4 - d; sabsA0 += fabsf(dl); if (dl < MARGIN) pcA += 1.f;
                        dl = ta5 - d; sabsA1 += fabsf(dl); if (dl < MARGIN) pcA += 1.f;
                        dl = ta6 - d; sabsA0 += fabsf(dl); if (dl < MARGIN) pcA += 1.f;
                    }
                }
            }
        }
        // pass B: cols outer, d from registers
        #pragma unroll
        for (int nt = 0; nt < 4; nt++) {
            #pragma unroll
            for (int v = 0; v < 2; v++) {
                const int c = wn * 32 + nt * 8 + 2 * q + v;
                float tb0 = s_tB[c][0], tb1 = s_tB[c][1], tb2 = s_tB[c][2];
                float tb3 = s_tB[c][3], tb4 = s_tB[c][4], tb5 = s_tB[c][5];
                float tb6 = s_tB[c][6];
                #pragma unroll
                for (int mt = 0; mt < 2; mt++) {
                    #pragma unroll
                    for (int h = 0; h < 2; h++) {
                        float d = acc[mt][nt][h * 2 + v];
                        float dl;
                        dl = tb0 - d; sabsB0 += fabsf(dl); if (dl < MARGIN) pcB += 1.f;
                        dl = tb1 - d; sabsB1 += fabsf(dl); if (dl < MARGIN) pcB += 1.f;
                        dl = tb2 - d; sabsB0 += fabsf(dl); if (dl < MARGIN) pcB += 1.f;
                        dl = tb3 - d; sabsB1 += fabsf(dl); if (dl < MARGIN) pcB += 1.f;
                        dl = tb4 - d; sabsB0 += fabsf(dl); if (dl < MARGIN) pcB += 1.f;
                        dl = tb5 - d; sabsB1 += fabsf(dl); if (dl < MARGIN) pcB += 1.f;
                        dl = tb6 - d; sabsB0 += fabsf(dl); if (dl < MARGIN) pcB += 1.f;
                    }
                }
            }
        }
    } else {
        // ======== diag path: mask = (col group) > (row group) ========
        #pragma unroll
        for (int mt = 0; mt < 2; mt++) {
            #pragma unroll
            for (int h = 0; h < 2; h++) {
                const int r  = wm * 32 + mt * 16 + h * 8 + g;
                const int rg = r >> 3;
                const float sqa = s_sqA[r];
                float ta0 = s_tA[r][0], ta1 = s_tA[r][1], ta2 = s_tA[r][2];
                float ta3 = s_tA[r][3], ta4 = s_tA[r][4], ta5 = s_tA[r][5];
                float ta6 = s_tA[r][6];
                #pragma unroll
                for (int nt = 0; nt < 4; nt++) {
                    #pragma unroll
                    for (int v = 0; v < 2; v++) {
                        const int c = wn * 32 + nt * 8 + 2 * q + v;
                        float m = ((c >> 3) > rg) ? 1.f : 0.f;
                        float d2 = fmaxf(sqa + sqb_r[nt * 2 + v] - 2.f * acc[mt][nt][h * 2 + v], 1e-12f);
                        float d  = fast_sqrt(d2);
                        acc[mt][nt][h * 2 + v] = d;
                        dnacc = fmaf(m, d, dnacc);
                        float dl;
                        dl = ta0 - d; sabsA0 = fmaf(m, fabsf(dl), sabsA0); if (dl < MARGIN) pcA += m;
                        dl = ta1 - d; sabsA1 = fmaf(m, fabsf(dl), sabsA1); if (dl < MARGIN) pcA += m;
                        dl = ta2 - d; sabsA0 = fmaf(m, fabsf(dl), sabsA0); if (dl < MARGIN) pcA += m;
                        dl = ta3 - d; sabsA1 = fmaf(m, fabsf(dl), sabsA1); if (dl < MARGIN) pcA += m;
                        dl = ta4 - d; sabsA0 = fmaf(m, fabsf(dl), sabsA0); if (dl < MARGIN) pcA += m;
                        dl = ta5 - d; sabsA1 = fmaf(m, fabsf(dl), sabsA1); if (dl < MARGIN) pcA += m;
                        dl = ta6 - d; sabsA0 = fmaf(m, fabsf(dl), sabsA0); if (dl < MARGIN) pcA += m;
                    }
                }
            }
        }
        #pragma unroll
        for (int nt = 0; nt < 4; nt++) {
            #pragma unroll
            for (int v = 0; v < 2; v++) {
                const int c  = wn * 32 + nt * 8 + 2 * q + v;
                const int cg = c >> 3;
                float tb0 = s_tB[c][0], tb1 = s_tB[c][1], tb2 = s_tB[c][2];
                float tb3 = s_tB[c][3], tb4 = s_tB[c][4], tb5 = s_tB[c][5];
                float tb6 = s_tB[c][6];
                #pragma unroll
                for (int mt = 0; mt < 2; mt++) {
                    #pragma unroll
                    for (int h = 0; h < 2; h++) {
                        const int r = wm * 32 + mt * 16 + h * 8 + g;
                        float m = (cg > (r >> 3)) ? 1.f : 0.f;
                        float d = acc[mt][nt][h * 2 + v];
                        float dl;
                        dl = tb0 - d; sabsB0 = fmaf(m, fabsf(dl), sabsB0); if (dl < MARGIN) pcB += m;
                        dl = tb1 - d; sabsB1 = fmaf(m, fabsf(dl), sabsB1); if (dl < MARGIN) pcB += m;
                        dl = tb2 - d; sabsB0 = fmaf(m, fabsf(dl), sabsB0); if (dl < MARGIN) pcB += m;
                        dl = tb3 - d; sabsB1 = fmaf(m, fabsf(dl), sabsB1); if (dl < MARGIN) pcB += m;
                        dl = tb4 - d; sabsB0 = fmaf(m, fabsf(dl), sabsB0); if (dl < MARGIN) pcB += m;
                        dl = tb5 - d; sabsB1 = fmaf(m, fabsf(dl), sabsB1); if (dl < MARGIN) pcB += m;
                        dl = tb6 - d; sabsB0 = fmaf(m, fabsf(dl), sabsB0); if (dl < MARGIN) pcB += m;
                    }
                }
            }
        }
    }

    // block reduction of (sabs, dn*2, pc, psum)
    float v4[4] = { (sabsA0 + sabsA1) + (sabsB0 + sabsB1),
                    2.f * dnacc,
                    pcA + pcB,
                    psum };
    #pragma unroll
    for (int r = 0; r < 4; r++) {
        float s = v4[r];
        #pragma unroll
        for (int o = 16; o > 0; o >>= 1) s += __shfl_xor_sync(0xffffffffu, s, o);
        if (lane == 0) s_red[r][warp] = s;
    }
    __syncthreads();

    if (warp == 0) {
        if (lane < 4) {
            float s = 0.f;
            #pragma unroll
            for (int w = 0; w < 16; w++) s += s_red[lane][w];
            // lane0->sabs(0), lane1->dn(3), lane2->pc(1), lane3->possum(2)
            const int dst[4] = {0, 3, 1, 2};
            atomicAdd(&g_acc[dst[lane]], (double)s);
        }
        __syncwarp();
        if (lane == 0) {
            __threadfence();
            unsigned old = atomicAdd(&g_count, 1u);
            if (old == (unsigned)(nBlocks - 1)) {
                double sabs   = atomicAdd(&g_acc[0], 0.0);
                double pc     = atomicAdd(&g_acc[1], 0.0);
                double possum = atomicAdd(&g_acc[2], 0.0);
                double dn     = atomicAdd(&g_acc[3], 0.0);
                int K = ni[0];
                double npos = (double)(K - 1);
                double nneg = (double)(N - K);
                double T_total = possum + (double)N * npos * (double)MARGIN;
                double hinge   = 0.5 * (nneg * T_total - npos * dn + sabs);
                double cnt     = (double)N * npos * nneg;
                out[0] = (float)(hinge / cnt);
                out[1] = (float)(pc / cnt);
                out[2] = (float)(possum / ((double)N * npos));
                out[3] = (float)(dn / ((double)N * nneg));
                g_acc[0] = 0.0; g_acc[1] = 0.0; g_acc[2] = 0.0; g_acc[3] = 0.0;
                __threadfence();
                g_count = 0u;
            }
        }
    }
}

// ---------------------------------------------------------------------------
extern "C" void kernel_launch(void* const* d_in, const int* in_sizes, int n_in,
                              void* d_out, int out_size) {
    const float* x  = (const float*)d_in[0];
    const int*   tg = (const int*)d_in[1];
    const int*   ni = (const int*)d_in[2];
    float*       out = (float*)d_out;

    const int N = in_sizes[1];
    const int D = in_sizes[0] / N;
    const int T = N / 128;
    const int nTiles = T * (T + 1) / 2;

    fused_kernel<<<nTiles, 512>>>(x, tg, ni, N, D, nTiles, out);
}